// round 16
// baseline (speedup 1.0000x reference)
#include <cuda_runtime.h>
#include <cuda_fp16.h>
#include <math.h>
#include <stdint.h>

#define F 128
#define MAXN 50000
#define MAXEGO 1250000
#define MAXE 700000
#define SCAN_TILE 1024

// fp16 activation buffers
__device__ __half g_xb[MAXN * F];
__device__ __half g_yb0[MAXN * F];
__device__ __half g_yb1[MAXN * F];
__device__ __half g_ah[MAXN * F];
// CSR scratch (list 0 = ego, list 1 = gin edges)
__device__ int g_deg[2 * MAXN];
__device__ int g_off[2 * (MAXN + 1)];
__device__ int g_adjEgo[MAXEGO];
__device__ int g_adjE[MAXE];
__device__ int g_rankEgo[MAXEGO];
__device__ int g_rankE[MAXE];

// ---------------------------------------------------------------------------
// fused: histogram+rank both edge lists + fp32->fp16 convert of x (grid-stride).
__global__ void build_front_kernel(const int* __restrict__ w0, int n0,
                                   const int* __restrict__ w1, int n1,
                                   int* __restrict__ deg0, int* __restrict__ deg1,
                                   int* __restrict__ rank0, int* __restrict__ rank1,
                                   const float* __restrict__ x, __half* __restrict__ y,
                                   int n4) {
    int i = blockIdx.x * blockDim.x + threadIdx.x;
    if (i < n0) rank0[i] = atomicAdd(&deg0[__ldg(w0 + i)], 1);
    if (i < n1) rank1[i] = atomicAdd(&deg1[__ldg(w1 + i)], 1);
    for (int j = i; j < n4; j += gridDim.x * blockDim.x) {
        float4 v = ((const float4*)x)[j];
        __half2 h0 = __floats2half2_rn(v.x, v.y);
        __half2 h1 = __floats2half2_rn(v.z, v.w);
        uint2 u;
        u.x = *(uint32_t*)&h0; u.y = *(uint32_t*)&h1;
        ((uint2*)y)[j] = u;
    }
}

// ---------------------------------------------------------------------------
// single-kernel exclusive scan: each block redundantly sums its prefix region,
// then scans its own tile. grid = (ntiles, 2 lists).
__global__ void scan_kernel(const int* __restrict__ deg, int n,
                            int* __restrict__ off, int nb) {
    __shared__ int red[8];
    __shared__ int ws[8];
    __shared__ int tb_s;
    const int list = blockIdx.y;
    const int* d = deg + list * n;
    int* of = off + list * (n + 1);
    const int b = blockIdx.x, t = threadIdx.x;
    const int lane = t & 31, wid = t >> 5;

    int pre = 0;
    const int4* d4 = (const int4*)d;
    for (int i = t; i < b * 256; i += 256) {
        int4 v = __ldg(d4 + i);
        pre += v.x + v.y + v.z + v.w;
    }
#pragma unroll
    for (int o = 16; o; o >>= 1) pre += __shfl_down_sync(0xffffffffu, pre, o);
    if (lane == 0) red[wid] = pre;
    __syncthreads();
    if (t == 0) {
        int s = 0;
#pragma unroll
        for (int i = 0; i < 8; i++) s += red[i];
        tb_s = s;
    }
    __syncthreads();
    const int tilebase = tb_s;

    int base = b * SCAN_TILE + t * 4;
    int v[4];
    int s = 0;
#pragma unroll
    for (int j = 0; j < 4; j++) {
        int i = base + j;
        v[j] = (i < n) ? __ldg(d + i) : 0;
        s += v[j];
    }
    int x = s;
#pragma unroll
    for (int o = 1; o < 32; o <<= 1) {
        int u = __shfl_up_sync(0xffffffffu, x, o);
        if (lane >= o) x += u;
    }
    if (lane == 31) ws[wid] = x;
    __syncthreads();
    if (wid == 0) {
        int w = (lane < 8) ? ws[lane] : 0;
#pragma unroll
        for (int o = 1; o < 8; o <<= 1) {
            int u = __shfl_up_sync(0xffffffffu, w, o);
            if (lane >= o) w += u;
        }
        if (lane < 8) ws[lane] = w;
    }
    __syncthreads();
    int run = tilebase + (x - s) + (wid ? ws[wid - 1] : 0);
#pragma unroll
    for (int j = 0; j < 4; j++) {
        int i = base + j;
        if (i < n) of[i] = run;
        run += v[j];
    }
    if (b == nb - 1 && t == 255) of[n] = run;
}

// atomic-free fill: adj[off[w] + rank] = r. PDL: off is the dependent input.
__global__ void fill2_kernel(const int* __restrict__ w0, const int* __restrict__ r0, int n0,
                             const int* __restrict__ w1, const int* __restrict__ r1, int n1,
                             const int* __restrict__ rank0, const int* __restrict__ rank1,
                             const int* __restrict__ off0, const int* __restrict__ off1,
                             int* __restrict__ adj0, int* __restrict__ adj1) {
    int i = blockIdx.x * blockDim.x + threadIdx.x;
    int w0v = 0, r0v = 0, k0v = 0, w1v = 0, r1v = 0, k1v = 0;
    if (i < n0) { w0v = __ldg(w0 + i); r0v = __ldg(r0 + i); k0v = __ldg(rank0 + i); }
    if (i < n1) { w1v = __ldg(w1 + i); r1v = __ldg(r1 + i); k1v = __ldg(rank1 + i); }
    cudaGridDependencySynchronize();
    if (i < n0) adj0[__ldg(off0 + w0v) + k0v] = r0v;
    if (i < n1) adj1[__ldg(off1 + w1v) + k1v] = r1v;
}

// ---------------------------------------------------------------------------
__device__ __forceinline__ void addh2(float2& a, uint32_t h) {
    float2 f = __half22float2(*(__half2*)&h);
    a.x += f.x; a.y += f.y;
}
__device__ __forceinline__ __half2 h2of(uint32_t u) { return *(__half2*)&u; }

// segsum over CSR, fp16 rows (128 halfs, uint2/lane) -> fp16 out.
// 8-edge fp16 HADD2 tree per group, fp32 fold once per group.
// PDL: off read in prologue; adj+x gather after sync.
template <bool SELF>
__global__ void segsum128h_kernel(const __half* __restrict__ x,
                                  const int* __restrict__ off,
                                  const int* __restrict__ adj,
                                  __half* __restrict__ out, int n, float scale) {
    int gw = (blockIdx.x * blockDim.x + threadIdx.x) >> 5;
    int lane = threadIdx.x & 31;
    int s = 0, e = 0;
    if (gw < n) { s = __ldg(off + gw); e = __ldg(off + gw + 1); }
    cudaGridDependencySynchronize();
    if (gw >= n) return;
    float2 acc0 = make_float2(0.f, 0.f), acc1 = make_float2(0.f, 0.f);
    if (SELF) {
        uint2 sv = __ldg((const uint2*)(x + (size_t)gw * 128) + lane);
        addh2(acc0, sv.x); addh2(acc1, sv.y);
    }
    for (int j = s; j < e; ) {
        int cnt = min(32, e - j);
        int my = (lane < cnt) ? __ldg(adj + j + lane) : 0;
        int k = 0;
        for (; k + 8 <= cnt; k += 8) {
            uint2 u[8];
#pragma unroll
            for (int q = 0; q < 8; q++) {
                int r = __shfl_sync(0xffffffffu, my, k + q);
                u[q] = __ldg((const uint2*)(x + (size_t)r * 128) + lane);
            }
            __half2 tx = __hadd2(
                __hadd2(__hadd2(h2of(u[0].x), h2of(u[1].x)),
                        __hadd2(h2of(u[2].x), h2of(u[3].x))),
                __hadd2(__hadd2(h2of(u[4].x), h2of(u[5].x)),
                        __hadd2(h2of(u[6].x), h2of(u[7].x))));
            __half2 ty = __hadd2(
                __hadd2(__hadd2(h2of(u[0].y), h2of(u[1].y)),
                        __hadd2(h2of(u[2].y), h2of(u[3].y))),
                __hadd2(__hadd2(h2of(u[4].y), h2of(u[5].y)),
                        __hadd2(h2of(u[6].y), h2of(u[7].y))));
            float2 fx = __half22float2(tx);
            float2 fy = __half22float2(ty);
            acc0.x += fx.x; acc0.y += fx.y;
            acc1.x += fy.x; acc1.y += fy.y;
        }
        if (k + 4 <= cnt) {
            uint2 u[4];
#pragma unroll
            for (int q = 0; q < 4; q++) {
                int r = __shfl_sync(0xffffffffu, my, k + q);
                u[q] = __ldg((const uint2*)(x + (size_t)r * 128) + lane);
            }
            __half2 tx = __hadd2(__hadd2(h2of(u[0].x), h2of(u[1].x)),
                                 __hadd2(h2of(u[2].x), h2of(u[3].x)));
            __half2 ty = __hadd2(__hadd2(h2of(u[0].y), h2of(u[1].y)),
                                 __hadd2(h2of(u[2].y), h2of(u[3].y)));
            float2 fx = __half22float2(tx);
            float2 fy = __half22float2(ty);
            acc0.x += fx.x; acc0.y += fx.y;
            acc1.x += fy.x; acc1.y += fy.y;
            k += 4;
        }
        for (; k < cnt; k++) {
            int r0 = __shfl_sync(0xffffffffu, my, k);
            uint2 u0 = __ldg((const uint2*)(x + (size_t)r0 * 128) + lane);
            addh2(acc0, u0.x); addh2(acc1, u0.y);
        }
        j += cnt;
    }
    __half2 h0 = __floats2half2_rn(acc0.x * scale, acc0.y * scale);
    __half2 h1 = __floats2half2_rn(acc1.x * scale, acc1.y * scale);
    uint2 o;
    o.x = *(uint32_t*)&h0; o.y = *(uint32_t*)&h1;
    *(uint2*)(out + (size_t)gw * 128 + lane * 4) = o;
}

// ---------------------------------------------------------------------------
__device__ __forceinline__ void mma_f16(float& c0, float& c1, float& c2, float& c3,
                                        uint32_t a0, uint32_t a1, uint32_t a2, uint32_t a3,
                                        uint32_t b0, uint32_t b1) {
    asm volatile(
        "mma.sync.aligned.m16n8k16.row.col.f32.f16.f16.f32 "
        "{%0,%1,%2,%3}, {%4,%5,%6,%7}, {%8,%9}, {%0,%1,%2,%3};"
        : "+f"(c0), "+f"(c1), "+f"(c2), "+f"(c3)
        : "r"(a0), "r"(a1), "r"(a2), "r"(a3), "r"(b0), "r"(b1));
}

// fp16 GEMM: C = relu(Ah @ W + b). PDL: W/bias staged before sync, A after.
__global__ void __launch_bounds__(256, 4)
gemm_h_kernel(const __half* __restrict__ Ah,
              const float* __restrict__ W, const float* __restrict__ bias,
              __half* __restrict__ Ch, int M) {
    constexpr int PWH = 136;
    constexpr int PAH = 136;
    __shared__ __half Wt[64 * PWH];
    __shared__ __half As[64 * PAH];
    __shared__ float bs[64];

    const int tid  = threadIdx.x;
    const int lane = tid & 31;
    const int warp = tid >> 5;
    const int cb   = blockIdx.y * 64;
    const int base = blockIdx.x * 64;

    {
        int tn = tid & 63;
        int gc = cb + tn;
        for (int kb = (tid >> 6) * 8; kb < 128; kb += 32) {
            __half tmp[8];
#pragma unroll
            for (int j = 0; j < 8; j++)
                tmp[j] = __float2half_rn(__ldg(W + (size_t)(kb + j) * 128 + gc));
            *(uint4*)(Wt + tn * PWH + kb) = *(uint4*)tmp;
        }
    }
    if (tid < 64) bs[tid] = __ldg(bias + cb + tid);

    cudaGridDependencySynchronize();

#pragma unroll
    for (int u = tid; u < 64 * 16; u += 256) {
        int rr = u >> 4, c8 = u & 15;
        int row = base + rr;
        uint4 hv = make_uint4(0u, 0u, 0u, 0u);
        if (row < M) hv = __ldg((const uint4*)(Ah + (size_t)row * 128) + c8);
        *(uint4*)(As + rr * PAH + c8 * 8) = hv;
    }
    __syncthreads();

    const int wr = warp >> 1, wc = warp & 1;
    const int g = lane >> 2, t = lane & 3;
    float acc[4][4];
#pragma unroll
    for (int nt = 0; nt < 4; nt++)
#pragma unroll
        for (int j = 0; j < 4; j++) acc[nt][j] = 0.f;

    const int r0 = wr * 16 + g;
    const __half* arow0 = As + r0 * PAH;
    const __half* arow1 = As + (r0 + 8) * PAH;
#pragma unroll
    for (int ks = 0; ks < 8; ks++) {
        const int k0 = ks * 16;
        uint32_t a0 = *(const uint32_t*)(arow0 + k0 + 2 * t);
        uint32_t a1 = *(const uint32_t*)(arow1 + k0 + 2 * t);
        uint32_t a2 = *(const uint32_t*)(arow0 + k0 + 2 * t + 8);
        uint32_t a3 = *(const uint32_t*)(arow1 + k0 + 2 * t + 8);
#pragma unroll
        for (int nt = 0; nt < 4; nt++) {
            int n = wc * 32 + nt * 8 + g;
            uint32_t b0 = *(const uint32_t*)(Wt + n * PWH + k0 + 2 * t);
            uint32_t b1 = *(const uint32_t*)(Wt + n * PWH + k0 + 2 * t + 8);
            mma_f16(acc[nt][0], acc[nt][1], acc[nt][2], acc[nt][3],
                    a0, a1, a2, a3, b0, b1);
        }
    }

    int gr0 = base + wr * 16 + g;
    int gr1 = gr0 + 8;
#pragma unroll
    for (int nt = 0; nt < 4; nt++) {
        int col = wc * 32 + nt * 8 + t * 2;
        float bx = bs[col], by = bs[col + 1];
        __half2 h0 = __floats2half2_rn(fmaxf(acc[nt][0] + bx, 0.f), fmaxf(acc[nt][1] + by, 0.f));
        __half2 h1 = __floats2half2_rn(fmaxf(acc[nt][2] + bx, 0.f), fmaxf(acc[nt][3] + by, 0.f));
        int gcol = cb + col;
        if (gr0 < M) *(__half2*)(Ch + (size_t)gr0 * 128 + gcol) = h0;
        if (gr1 < M) *(__half2*)(Ch + (size_t)gr1 * 128 + gcol) = h1;
    }
}

// final GEMM + bias + log_softmax fused. PDL: W/bias staged before sync.
__global__ void __launch_bounds__(256, 4)
gemm47_lsm_kernel(const __half* __restrict__ Ah, const float* __restrict__ W,
                  const float* __restrict__ bias,
                  float* __restrict__ outp, int M, int nca) {
    constexpr int PWH = 136;
    constexpr int PAH = 136;
    constexpr int LP = 65;
    __shared__ __half Wt[64 * PWH];   // reused as logits after MMA
    __shared__ __half As[64 * PAH];
    __shared__ float bs[64];

    const int tid  = threadIdx.x;
    const int lane = tid & 31;
    const int warp = tid >> 5;
    const int base = blockIdx.x * 64;

    {
        int tn = tid & 63;
        for (int kb = (tid >> 6) * 8; kb < 128; kb += 32) {
            __half tmp[8];
#pragma unroll
            for (int j = 0; j < 8; j++) {
                float w = (tn < nca) ? __ldg(W + (size_t)(kb + j) * nca + tn) : 0.f;
                tmp[j] = __float2half_rn(w);
            }
            *(uint4*)(Wt + tn * PWH + kb) = *(uint4*)tmp;
        }
    }
    if (tid < 64) bs[tid] = (tid < nca) ? __ldg(bias + tid) : 0.f;

    cudaGridDependencySynchronize();

#pragma unroll
    for (int u = tid; u < 64 * 16; u += 256) {
        int rr = u >> 4, c8 = u & 15;
        int row = base + rr;
        uint4 hv = make_uint4(0u, 0u, 0u, 0u);
        if (row < M) hv = __ldg((const uint4*)(Ah + (size_t)row * 128) + c8);
        *(uint4*)(As + rr * PAH + c8 * 8) = hv;
    }
    __syncthreads();

    const int wr = warp >> 1, wc = warp & 1;
    const int g = lane >> 2, t = lane & 3;
    float acc[4][4];
#pragma unroll
    for (int nt = 0; nt < 4; nt++)
#pragma unroll
        for (int j = 0; j < 4; j++) acc[nt][j] = 0.f;

    const int r0 = wr * 16 + g;
    const __half* arow0 = As + r0 * PAH;
    const __half* arow1 = As + (r0 + 8) * PAH;
#pragma unroll
    for (int ks = 0; ks < 8; ks++) {
        const int k0 = ks * 16;
        uint32_t a0 = *(const uint32_t*)(arow0 + k0 + 2 * t);
        uint32_t a1 = *(const uint32_t*)(arow1 + k0 + 2 * t);
        uint32_t a2 = *(const uint32_t*)(arow0 + k0 + 2 * t + 8);
        uint32_t a3 = *(const uint32_t*)(arow1 + k0 + 2 * t + 8);
#pragma unroll
        for (int nt = 0; nt < 4; nt++) {
            int n = wc * 32 + nt * 8 + g;
            uint32_t b0 = *(const uint32_t*)(Wt + n * PWH + k0 + 2 * t);
            uint32_t b1 = *(const uint32_t*)(Wt + n * PWH + k0 + 2 * t + 8);
            mma_f16(acc[nt][0], acc[nt][1], acc[nt][2], acc[nt][3],
                    a0, a1, a2, a3, b0, b1);
        }
    }
    __syncthreads();  // all Wt reads done; reuse as logits

    float* lg = (float*)Wt;  // [64][LP]
#pragma unroll
    for (int nt = 0; nt < 4; nt++) {
        int col = wc * 32 + nt * 8 + t * 2;
        float bx = bs[col], by = bs[col + 1];
        int lr0 = wr * 16 + g, lr1 = lr0 + 8;
        lg[lr0 * LP + col]     = acc[nt][0] + bx;
        lg[lr0 * LP + col + 1] = acc[nt][1] + by;
        lg[lr1 * LP + col]     = acc[nt][2] + bx;
        lg[lr1 * LP + col + 1] = acc[nt][3] + by;
    }
    __syncthreads();

    for (int r = warp; r < 64; r += 8) {
        int row = base + r;
        if (row >= M) continue;
        int c2 = lane + 32;
        float v1 = (lane < nca) ? lg[r * LP + lane] : -INFINITY;
        float v2 = (c2 < nca)   ? lg[r * LP + c2]   : -INFINITY;
        float mx = fmaxf(v1, v2);
#pragma unroll
        for (int o = 16; o; o >>= 1) mx = fmaxf(mx, __shfl_xor_sync(0xffffffffu, mx, o));
        float s = ((lane < nca) ? expf(v1 - mx) : 0.f) + ((c2 < nca) ? expf(v2 - mx) : 0.f);
#pragma unroll
        for (int o = 16; o; o >>= 1) s += __shfl_xor_sync(0xffffffffu, s, o);
        float lgn = logf(s) + mx;
        float* orow = outp + (size_t)row * nca;
        if (lane < nca) orow[lane] = v1 - lgn;
        if (c2 < nca)   orow[c2]   = v2 - lgn;
    }
}

// ---------------------------------------------------------------------------
template <typename... Args>
static void launch_pdl(void (*kern)(Args...), dim3 g, dim3 b, Args... args) {
    cudaLaunchConfig_t cfg = {};
    cfg.gridDim = g;
    cfg.blockDim = b;
    cfg.dynamicSmemBytes = 0;
    cfg.stream = 0;
    cudaLaunchAttribute attr[1];
    attr[0].id = cudaLaunchAttributeProgrammaticStreamSerialization;
    attr[0].val.programmaticStreamSerializationAllowed = 1;
    cfg.attrs = attr;
    cfg.numAttrs = 1;
    cudaLaunchKernelEx(&cfg, kern, args...);
}

extern "C" void kernel_launch(void* const* d_in, const int* in_sizes, int n_in,
                              void* d_out, int out_size) {
    const float* x_in   = (const float*)d_in[0];
    const int*   ei     = (const int*)d_in[1];
    const int*   ego    = (const int*)d_in[2];
    const float* W_ego0 = (const float*)d_in[3];
    const float* b_ego0 = (const float*)d_in[4];
    const float* W_gin0 = (const float*)d_in[5];
    const float* b_gin0 = (const float*)d_in[6];
    const float* W_ego1 = (const float*)d_in[7];
    const float* b_ego1 = (const float*)d_in[8];
    const float* W_gin1 = (const float*)d_in[9];
    const float* b_gin1 = (const float*)d_in[10];

    int N    = in_sizes[0] / F;
    int E    = in_sizes[1] / 2;
    int EGO  = in_sizes[2] / 2;
    int OUTC = in_sizes[10];
    float invN = 1.0f / (float)N;

    __half *xb, *yb0, *yb1, *ah;
    int *deg, *off, *adjEgo, *adjE, *rankEgo, *rankE;
    cudaGetSymbolAddress((void**)&xb, g_xb);
    cudaGetSymbolAddress((void**)&yb0, g_yb0);
    cudaGetSymbolAddress((void**)&yb1, g_yb1);
    cudaGetSymbolAddress((void**)&ah, g_ah);
    cudaGetSymbolAddress((void**)&deg, g_deg);
    cudaGetSymbolAddress((void**)&off, g_off);
    cudaGetSymbolAddress((void**)&adjEgo, g_adjEgo);
    cudaGetSymbolAddress((void**)&adjE, g_adjE);
    cudaGetSymbolAddress((void**)&rankEgo, g_rankEgo);
    cudaGetSymbolAddress((void**)&rankE, g_rankE);

    int *degEgo = deg, *degE = deg + N;
    int *offEgo = off, *offE = off + (N + 1);

    dim3 g128((N + 63) / 64, 2);
    dim3 gf((N + 63) / 64, 1);
    dim3 sg((N * 32 + 255) / 256, 1);
    int ntiles = (N + SCAN_TILE - 1) / SCAN_TILE;
    int maxE = (EGO > E) ? EGO : E;
    dim3 eb((maxE + 255) / 256, 1);
    dim3 scang(ntiles, 2);
    dim3 blk(256, 1, 1);

    // ---- CSR build + fp16 convert ----
    cudaMemsetAsync(deg, 0, 2 * N * sizeof(int), 0);
    build_front_kernel<<<eb, 256>>>(ego, EGO, ei + E, E, degEgo, degE,
                                    rankEgo, rankE, x_in, xb, N * F / 4);
    scan_kernel<<<scang, 256>>>(deg, N, off, ntiles);
    launch_pdl(fill2_kernel, eb, blk,
               (const int*)ego, (const int*)(ego + EGO), EGO,
               (const int*)(ei + E), (const int*)ei, E,
               (const int*)rankEgo, (const int*)rankE,
               (const int*)offEgo, (const int*)offE, adjEgo, adjE);

    // ---- layer 0: Ego ----
    launch_pdl(&segsum128h_kernel<false>, sg, blk,
               (const __half*)xb, (const int*)offEgo, (const int*)adjEgo, ah, N, invN);
    launch_pdl(gemm_h_kernel, g128, blk,
               (const __half*)ah, W_ego0, b_ego0, yb0, N);
    // ---- layer 0: GIN ----
    launch_pdl(&segsum128h_kernel<true>, sg, blk,
               (const __half*)yb0, (const int*)offE, (const int*)adjE, ah, N, 1.0f);
    launch_pdl(gemm_h_kernel, g128, blk,
               (const __half*)ah, W_gin0, b_gin0, yb1, N);
    // ---- layer 1: Ego ----
    launch_pdl(&segsum128h_kernel<false>, sg, blk,
               (const __half*)yb1, (const int*)offEgo, (const int*)adjEgo, ah, N, invN);
    launch_pdl(gemm_h_kernel, g128, blk,
               (const __half*)ah, W_ego1, b_ego1, yb0, N);
    // ---- layer 1: GIN (direct x+aggr, fused GEMM+bias+log_softmax) ----
    launch_pdl(&segsum128h_kernel<true>, sg, blk,
               (const __half*)yb0, (const int*)offE, (const int*)adjE, ah, N, 1.0f);
    launch_pdl(gemm47_lsm_kernel, gf, blk,
               (const __half*)ah, W_gin1, b_gin1, (float*)d_out, N, OUTC);
}

// round 17
// speedup vs baseline: 1.0762x; 1.0762x over previous
#include <cuda_runtime.h>
#include <cuda_fp16.h>
#include <math.h>
#include <stdint.h>

#define F 128
#define MAXN 50000
#define MAXEGO 1250000
#define MAXE 700000
#define SCAN_TILE 1024

// fp16 activation buffers
__device__ __half g_xb[MAXN * F];
__device__ __half g_yb0[MAXN * F];
__device__ __half g_yb1[MAXN * F];
__device__ __half g_ah[MAXN * F];
// CSR scratch (list 0 = ego, list 1 = gin edges)
__device__ int g_deg[2 * MAXN];
__device__ int g_off[2 * (MAXN + 1)];
__device__ int g_adjEgo[MAXEGO];
__device__ int g_adjE[MAXE];
__device__ int g_rankEgo[MAXEGO];
__device__ int g_rankE[MAXE];

// ---------------------------------------------------------------------------
// fused: histogram+rank both edge lists + fp32->fp16 convert of x (grid-stride).
__global__ void build_front_kernel(const int* __restrict__ w0, int n0,
                                   const int* __restrict__ w1, int n1,
                                   int* __restrict__ deg0, int* __restrict__ deg1,
                                   int* __restrict__ rank0, int* __restrict__ rank1,
                                   const float* __restrict__ x, __half* __restrict__ y,
                                   int n4) {
    int i = blockIdx.x * blockDim.x + threadIdx.x;
    if (i < n0) rank0[i] = atomicAdd(&deg0[__ldg(w0 + i)], 1);
    if (i < n1) rank1[i] = atomicAdd(&deg1[__ldg(w1 + i)], 1);
    for (int j = i; j < n4; j += gridDim.x * blockDim.x) {
        float4 v = ((const float4*)x)[j];
        __half2 h0 = __floats2half2_rn(v.x, v.y);
        __half2 h1 = __floats2half2_rn(v.z, v.w);
        uint2 u;
        u.x = *(uint32_t*)&h0; u.y = *(uint32_t*)&h1;
        ((uint2*)y)[j] = u;
    }
}

// ---------------------------------------------------------------------------
// single-kernel exclusive scan: each block redundantly sums its prefix region,
// then scans its own tile. grid = (ntiles, 2 lists).
__global__ void scan_kernel(const int* __restrict__ deg, int n,
                            int* __restrict__ off, int nb) {
    __shared__ int red[8];
    __shared__ int ws[8];
    __shared__ int tb_s;
    const int list = blockIdx.y;
    const int* d = deg + list * n;
    int* of = off + list * (n + 1);
    const int b = blockIdx.x, t = threadIdx.x;
    const int lane = t & 31, wid = t >> 5;

    int pre = 0;
    const int4* d4 = (const int4*)d;
    for (int i = t; i < b * 256; i += 256) {
        int4 v = __ldg(d4 + i);
        pre += v.x + v.y + v.z + v.w;
    }
#pragma unroll
    for (int o = 16; o; o >>= 1) pre += __shfl_down_sync(0xffffffffu, pre, o);
    if (lane == 0) red[wid] = pre;
    __syncthreads();
    if (t == 0) {
        int s = 0;
#pragma unroll
        for (int i = 0; i < 8; i++) s += red[i];
        tb_s = s;
    }
    __syncthreads();
    const int tilebase = tb_s;

    int base = b * SCAN_TILE + t * 4;
    int v[4];
    int s = 0;
#pragma unroll
    for (int j = 0; j < 4; j++) {
        int i = base + j;
        v[j] = (i < n) ? __ldg(d + i) : 0;
        s += v[j];
    }
    int x = s;
#pragma unroll
    for (int o = 1; o < 32; o <<= 1) {
        int u = __shfl_up_sync(0xffffffffu, x, o);
        if (lane >= o) x += u;
    }
    if (lane == 31) ws[wid] = x;
    __syncthreads();
    if (wid == 0) {
        int w = (lane < 8) ? ws[lane] : 0;
#pragma unroll
        for (int o = 1; o < 8; o <<= 1) {
            int u = __shfl_up_sync(0xffffffffu, w, o);
            if (lane >= o) w += u;
        }
        if (lane < 8) ws[lane] = w;
    }
    __syncthreads();
    int run = tilebase + (x - s) + (wid ? ws[wid - 1] : 0);
#pragma unroll
    for (int j = 0; j < 4; j++) {
        int i = base + j;
        if (i < n) of[i] = run;
        run += v[j];
    }
    if (b == nb - 1 && t == 255) of[n] = run;
}

// atomic-free fill: adj[off[w] + rank] = r. PDL: off is the dependent input.
__global__ void fill2_kernel(const int* __restrict__ w0, const int* __restrict__ r0, int n0,
                             const int* __restrict__ w1, const int* __restrict__ r1, int n1,
                             const int* __restrict__ rank0, const int* __restrict__ rank1,
                             const int* __restrict__ off0, const int* __restrict__ off1,
                             int* __restrict__ adj0, int* __restrict__ adj1) {
    int i = blockIdx.x * blockDim.x + threadIdx.x;
    int w0v = 0, r0v = 0, k0v = 0, w1v = 0, r1v = 0, k1v = 0;
    if (i < n0) { w0v = __ldg(w0 + i); r0v = __ldg(r0 + i); k0v = __ldg(rank0 + i); }
    if (i < n1) { w1v = __ldg(w1 + i); r1v = __ldg(r1 + i); k1v = __ldg(rank1 + i); }
    cudaGridDependencySynchronize();
    if (i < n0) adj0[__ldg(off0 + w0v) + k0v] = r0v;
    if (i < n1) adj1[__ldg(off1 + w1v) + k1v] = r1v;
}

// ---------------------------------------------------------------------------
__device__ __forceinline__ void addh2(float2& a, uint32_t h) {
    float2 f = __half22float2(*(__half2*)&h);
    a.x += f.x; a.y += f.y;
}
__device__ __forceinline__ __half2 h2of(uint32_t u) { return *(__half2*)&u; }

// segsum over CSR, fp16 rows (128 halfs, uint2/lane) -> fp16 out.
// 4-edge fp16 HADD2 tree per group, fp32 fold once per group (proven sweet spot:
// regs=30, occ=80%; wider groups regress via register pressure).
// PDL: off read in prologue; adj+x gather after sync.
template <bool SELF>
__global__ void __launch_bounds__(256, 6)
segsum128h_kernel(const __half* __restrict__ x,
                  const int* __restrict__ off,
                  const int* __restrict__ adj,
                  __half* __restrict__ out, int n, float scale) {
    int gw = (blockIdx.x * blockDim.x + threadIdx.x) >> 5;
    int lane = threadIdx.x & 31;
    int s = 0, e = 0;
    if (gw < n) { s = __ldg(off + gw); e = __ldg(off + gw + 1); }
    cudaGridDependencySynchronize();
    if (gw >= n) return;
    float2 acc0 = make_float2(0.f, 0.f), acc1 = make_float2(0.f, 0.f);
    if (SELF) {
        uint2 sv = __ldg((const uint2*)(x + (size_t)gw * 128) + lane);
        addh2(acc0, sv.x); addh2(acc1, sv.y);
    }
    for (int j = s; j < e; ) {
        int cnt = min(32, e - j);
        int my = (lane < cnt) ? __ldg(adj + j + lane) : 0;
        int k = 0;
        for (; k + 4 <= cnt; k += 4) {
            int r0 = __shfl_sync(0xffffffffu, my, k);
            int r1 = __shfl_sync(0xffffffffu, my, k + 1);
            int r2 = __shfl_sync(0xffffffffu, my, k + 2);
            int r3 = __shfl_sync(0xffffffffu, my, k + 3);
            uint2 u0 = __ldg((const uint2*)(x + (size_t)r0 * 128) + lane);
            uint2 u1 = __ldg((const uint2*)(x + (size_t)r1 * 128) + lane);
            uint2 u2 = __ldg((const uint2*)(x + (size_t)r2 * 128) + lane);
            uint2 u3 = __ldg((const uint2*)(x + (size_t)r3 * 128) + lane);
            __half2 tx = __hadd2(__hadd2(h2of(u0.x), h2of(u1.x)),
                                 __hadd2(h2of(u2.x), h2of(u3.x)));
            __half2 ty = __hadd2(__hadd2(h2of(u0.y), h2of(u1.y)),
                                 __hadd2(h2of(u2.y), h2of(u3.y)));
            float2 fx = __half22float2(tx);
            float2 fy = __half22float2(ty);
            acc0.x += fx.x; acc0.y += fx.y;
            acc1.x += fy.x; acc1.y += fy.y;
        }
        for (; k < cnt; k++) {
            int r0 = __shfl_sync(0xffffffffu, my, k);
            uint2 u0 = __ldg((const uint2*)(x + (size_t)r0 * 128) + lane);
            addh2(acc0, u0.x); addh2(acc1, u0.y);
        }
        j += cnt;
    }
    __half2 h0 = __floats2half2_rn(acc0.x * scale, acc0.y * scale);
    __half2 h1 = __floats2half2_rn(acc1.x * scale, acc1.y * scale);
    uint2 o;
    o.x = *(uint32_t*)&h0; o.y = *(uint32_t*)&h1;
    *(uint2*)(out + (size_t)gw * 128 + lane * 4) = o;
}

// ---------------------------------------------------------------------------
__device__ __forceinline__ void mma_f16(float& c0, float& c1, float& c2, float& c3,
                                        uint32_t a0, uint32_t a1, uint32_t a2, uint32_t a3,
                                        uint32_t b0, uint32_t b1) {
    asm volatile(
        "mma.sync.aligned.m16n8k16.row.col.f32.f16.f16.f32 "
        "{%0,%1,%2,%3}, {%4,%5,%6,%7}, {%8,%9}, {%0,%1,%2,%3};"
        : "+f"(c0), "+f"(c1), "+f"(c2), "+f"(c3)
        : "r"(a0), "r"(a1), "r"(a2), "r"(a3), "r"(b0), "r"(b1));
}

// fp16 GEMM: C = relu(Ah @ W + b). PDL: W/bias staged before sync, A after.
__global__ void __launch_bounds__(256, 4)
gemm_h_kernel(const __half* __restrict__ Ah,
              const float* __restrict__ W, const float* __restrict__ bias,
              __half* __restrict__ Ch, int M) {
    constexpr int PWH = 136;
    constexpr int PAH = 136;
    __shared__ __half Wt[64 * PWH];
    __shared__ __half As[64 * PAH];
    __shared__ float bs[64];

    const int tid  = threadIdx.x;
    const int lane = tid & 31;
    const int warp = tid >> 5;
    const int cb   = blockIdx.y * 64;
    const int base = blockIdx.x * 64;

    {
        int tn = tid & 63;
        int gc = cb + tn;
        for (int kb = (tid >> 6) * 8; kb < 128; kb += 32) {
            __half tmp[8];
#pragma unroll
            for (int j = 0; j < 8; j++)
                tmp[j] = __float2half_rn(__ldg(W + (size_t)(kb + j) * 128 + gc));
            *(uint4*)(Wt + tn * PWH + kb) = *(uint4*)tmp;
        }
    }
    if (tid < 64) bs[tid] = __ldg(bias + cb + tid);

    cudaGridDependencySynchronize();

#pragma unroll
    for (int u = tid; u < 64 * 16; u += 256) {
        int rr = u >> 4, c8 = u & 15;
        int row = base + rr;
        uint4 hv = make_uint4(0u, 0u, 0u, 0u);
        if (row < M) hv = __ldg((const uint4*)(Ah + (size_t)row * 128) + c8);
        *(uint4*)(As + rr * PAH + c8 * 8) = hv;
    }
    __syncthreads();

    const int wr = warp >> 1, wc = warp & 1;
    const int g = lane >> 2, t = lane & 3;
    float acc[4][4];
#pragma unroll
    for (int nt = 0; nt < 4; nt++)
#pragma unroll
        for (int j = 0; j < 4; j++) acc[nt][j] = 0.f;

    const int r0 = wr * 16 + g;
    const __half* arow0 = As + r0 * PAH;
    const __half* arow1 = As + (r0 + 8) * PAH;
#pragma unroll
    for (int ks = 0; ks < 8; ks++) {
        const int k0 = ks * 16;
        uint32_t a0 = *(const uint32_t*)(arow0 + k0 + 2 * t);
        uint32_t a1 = *(const uint32_t*)(arow1 + k0 + 2 * t);
        uint32_t a2 = *(const uint32_t*)(arow0 + k0 + 2 * t + 8);
        uint32_t a3 = *(const uint32_t*)(arow1 + k0 + 2 * t + 8);
#pragma unroll
        for (int nt = 0; nt < 4; nt++) {
            int n = wc * 32 + nt * 8 + g;
            uint32_t b0 = *(const uint32_t*)(Wt + n * PWH + k0 + 2 * t);
            uint32_t b1 = *(const uint32_t*)(Wt + n * PWH + k0 + 2 * t + 8);
            mma_f16(acc[nt][0], acc[nt][1], acc[nt][2], acc[nt][3],
                    a0, a1, a2, a3, b0, b1);
        }
    }

    int gr0 = base + wr * 16 + g;
    int gr1 = gr0 + 8;
#pragma unroll
    for (int nt = 0; nt < 4; nt++) {
        int col = wc * 32 + nt * 8 + t * 2;
        float bx = bs[col], by = bs[col + 1];
        __half2 h0 = __floats2half2_rn(fmaxf(acc[nt][0] + bx, 0.f), fmaxf(acc[nt][1] + by, 0.f));
        __half2 h1 = __floats2half2_rn(fmaxf(acc[nt][2] + bx, 0.f), fmaxf(acc[nt][3] + by, 0.f));
        int gcol = cb + col;
        if (gr0 < M) *(__half2*)(Ch + (size_t)gr0 * 128 + gcol) = h0;
        if (gr1 < M) *(__half2*)(Ch + (size_t)gr1 * 128 + gcol) = h1;
    }
}

// final GEMM + bias + log_softmax fused. PDL: W/bias staged before sync.
__global__ void __launch_bounds__(256, 4)
gemm47_lsm_kernel(const __half* __restrict__ Ah, const float* __restrict__ W,
                  const float* __restrict__ bias,
                  float* __restrict__ outp, int M, int nca) {
    constexpr int PWH = 136;
    constexpr int PAH = 136;
    constexpr int LP = 65;
    __shared__ __half Wt[64 * PWH];   // reused as logits after MMA
    __shared__ __half As[64 * PAH];
    __shared__ float bs[64];

    const int tid  = threadIdx.x;
    const int lane = tid & 31;
    const int warp = tid >> 5;
    const int base = blockIdx.x * 64;

    {
        int tn = tid & 63;
        for (int kb = (tid >> 6) * 8; kb < 128; kb += 32) {
            __half tmp[8];
#pragma unroll
            for (int j = 0; j < 8; j++) {
                float w = (tn < nca) ? __ldg(W + (size_t)(kb + j) * nca + tn) : 0.f;
                tmp[j] = __float2half_rn(w);
            }
            *(uint4*)(Wt + tn * PWH + kb) = *(uint4*)tmp;
        }
    }
    if (tid < 64) bs[tid] = (tid < nca) ? __ldg(bias + tid) : 0.f;

    cudaGridDependencySynchronize();

#pragma unroll
    for (int u = tid; u < 64 * 16; u += 256) {
        int rr = u >> 4, c8 = u & 15;
        int row = base + rr;
        uint4 hv = make_uint4(0u, 0u, 0u, 0u);
        if (row < M) hv = __ldg((const uint4*)(Ah + (size_t)row * 128) + c8);
        *(uint4*)(As + rr * PAH + c8 * 8) = hv;
    }
    __syncthreads();

    const int wr = warp >> 1, wc = warp & 1;
    const int g = lane >> 2, t = lane & 3;
    float acc[4][4];
#pragma unroll
    for (int nt = 0; nt < 4; nt++)
#pragma unroll
        for (int j = 0; j < 4; j++) acc[nt][j] = 0.f;

    const int r0 = wr * 16 + g;
    const __half* arow0 = As + r0 * PAH;
    const __half* arow1 = As + (r0 + 8) * PAH;
#pragma unroll
    for (int ks = 0; ks < 8; ks++) {
        const int k0 = ks * 16;
        uint32_t a0 = *(const uint32_t*)(arow0 + k0 + 2 * t);
        uint32_t a1 = *(const uint32_t*)(arow1 + k0 + 2 * t);
        uint32_t a2 = *(const uint32_t*)(arow0 + k0 + 2 * t + 8);
        uint32_t a3 = *(const uint32_t*)(arow1 + k0 + 2 * t + 8);
#pragma unroll
        for (int nt = 0; nt < 4; nt++) {
            int n = wc * 32 + nt * 8 + g;
            uint32_t b0 = *(const uint32_t*)(Wt + n * PWH + k0 + 2 * t);
            uint32_t b1 = *(const uint32_t*)(Wt + n * PWH + k0 + 2 * t + 8);
            mma_f16(acc[nt][0], acc[nt][1], acc[nt][2], acc[nt][3],
                    a0, a1, a2, a3, b0, b1);
        }
    }
    __syncthreads();  // all Wt reads done; reuse as logits

    float* lg = (float*)Wt;  // [64][LP]
#pragma unroll
    for (int nt = 0; nt < 4; nt++) {
        int col = wc * 32 + nt * 8 + t * 2;
        float bx = bs[col], by = bs[col + 1];
        int lr0 = wr * 16 + g, lr1 = lr0 + 8;
        lg[lr0 * LP + col]     = acc[nt][0] + bx;
        lg[lr0 * LP + col + 1] = acc[nt][1] + by;
        lg[lr1 * LP + col]     = acc[nt][2] + bx;
        lg[lr1 * LP + col + 1] = acc[nt][3] + by;
    }
    __syncthreads();

    for (int r = warp; r < 64; r += 8) {
        int row = base + r;
        if (row >= M) continue;
        int c2 = lane + 32;
        float v1 = (lane < nca) ? lg[r * LP + lane] : -INFINITY;
        float v2 = (c2 < nca)   ? lg[r * LP + c2]   : -INFINITY;
        float mx = fmaxf(v1, v2);
#pragma unroll
        for (int o = 16; o; o >>= 1) mx = fmaxf(mx, __shfl_xor_sync(0xffffffffu, mx, o));
        float s = ((lane < nca) ? expf(v1 - mx) : 0.f) + ((c2 < nca) ? expf(v2 - mx) : 0.f);
#pragma unroll
        for (int o = 16; o; o >>= 1) s += __shfl_xor_sync(0xffffffffu, s, o);
        float lgn = logf(s) + mx;
        float* orow = outp + (size_t)row * nca;
        if (lane < nca) orow[lane] = v1 - lgn;
        if (c2 < nca)   orow[c2]   = v2 - lgn;
    }
}

// ---------------------------------------------------------------------------
template <typename... Args>
static void launch_pdl(void (*kern)(Args...), dim3 g, dim3 b, Args... args) {
    cudaLaunchConfig_t cfg = {};
    cfg.gridDim = g;
    cfg.blockDim = b;
    cfg.dynamicSmemBytes = 0;
    cfg.stream = 0;
    cudaLaunchAttribute attr[1];
    attr[0].id = cudaLaunchAttributeProgrammaticStreamSerialization;
    attr[0].val.programmaticStreamSerializationAllowed = 1;
    cfg.attrs = attr;
    cfg.numAttrs = 1;
    cudaLaunchKernelEx(&cfg, kern, args...);
}

extern "C" void kernel_launch(void* const* d_in, const int* in_sizes, int n_in,
                              void* d_out, int out_size) {
    const float* x_in   = (const float*)d_in[0];
    const int*   ei     = (const int*)d_in[1];
    const int*   ego    = (const int*)d_in[2];
    const float* W_ego0 = (const float*)d_in[3];
    const float* b_ego0 = (const float*)d_in[4];
    const float* W_gin0 = (const float*)d_in[5];
    const float* b_gin0 = (const float*)d_in[6];
    const float* W_ego1 = (const float*)d_in[7];
    const float* b_ego1 = (const float*)d_in[8];
    const float* W_gin1 = (const float*)d_in[9];
    const float* b_gin1 = (const float*)d_in[10];

    int N    = in_sizes[0] / F;
    int E    = in_sizes[1] / 2;
    int EGO  = in_sizes[2] / 2;
    int OUTC = in_sizes[10];
    float invN = 1.0f / (float)N;

    __half *xb, *yb0, *yb1, *ah;
    int *deg, *off, *adjEgo, *adjE, *rankEgo, *rankE;
    cudaGetSymbolAddress((void**)&xb, g_xb);
    cudaGetSymbolAddress((void**)&yb0, g_yb0);
    cudaGetSymbolAddress((void**)&yb1, g_yb1);
    cudaGetSymbolAddress((void**)&ah, g_ah);
    cudaGetSymbolAddress((void**)&deg, g_deg);
    cudaGetSymbolAddress((void**)&off, g_off);
    cudaGetSymbolAddress((void**)&adjEgo, g_adjEgo);
    cudaGetSymbolAddress((void**)&adjE, g_adjE);
    cudaGetSymbolAddress((void**)&rankEgo, g_rankEgo);
    cudaGetSymbolAddress((void**)&rankE, g_rankE);

    int *degEgo = deg, *degE = deg + N;
    int *offEgo = off, *offE = off + (N + 1);

    dim3 g128((N + 63) / 64, 2);
    dim3 gf((N + 63) / 64, 1);
    dim3 sg((N * 32 + 255) / 256, 1);
    int ntiles = (N + SCAN_TILE - 1) / SCAN_TILE;
    int maxE = (EGO > E) ? EGO : E;
    dim3 eb((maxE + 255) / 256, 1);
    dim3 scang(ntiles, 2);
    dim3 blk(256, 1, 1);

    // ---- CSR build + fp16 convert ----
    cudaMemsetAsync(deg, 0, 2 * N * sizeof(int), 0);
    build_front_kernel<<<eb, 256>>>(ego, EGO, ei + E, E, degEgo, degE,
                                    rankEgo, rankE, x_in, xb, N * F / 4);
    scan_kernel<<<scang, 256>>>(deg, N, off, ntiles);
    launch_pdl(fill2_kernel, eb, blk,
               (const int*)ego, (const int*)(ego + EGO), EGO,
               (const int*)(ei + E), (const int*)ei, E,
               (const int*)rankEgo, (const int*)rankE,
               (const int*)offEgo, (const int*)offE, adjEgo, adjE);

    // ---- layer 0: Ego ----
    launch_pdl(&segsum128h_kernel<false>, sg, blk,
               (const __half*)xb, (const int*)offEgo, (const int*)adjEgo, ah, N, invN);
    launch_pdl(gemm_h_kernel, g128, blk,
               (const __half*)ah, W_ego0, b_ego0, yb0, N);
    // ---- layer 0: GIN ----
    launch_pdl(&segsum128h_kernel<true>, sg, blk,
               (const __half*)yb0, (const int*)offE, (const int*)adjE, ah, N, 1.0f);
    launch_pdl(gemm_h_kernel, g128, blk,
               (const __half*)ah, W_gin0, b_gin0, yb1, N);
    // ---- layer 1: Ego ----
    launch_pdl(&segsum128h_kernel<false>, sg, blk,
               (const __half*)yb1, (const int*)offEgo, (const int*)adjEgo, ah, N, invN);
    launch_pdl(gemm_h_kernel, g128, blk,
               (const __half*)ah, W_ego1, b_ego1, yb0, N);
    // ---- layer 1: GIN (direct x+aggr, fused GEMM+bias+log_softmax) ----
    launch_pdl(&segsum128h_kernel<true>, sg, blk,
               (const __half*)yb0, (const int*)offE, (const int*)adjE, ah, N, 1.0f);
    launch_pdl(gemm47_lsm_kernel, gf, blk,
               (const __half*)ah, W_gin1, b_gin1, (float*)d_out, N, OUTC);
}